// round 1
// baseline (speedup 1.0000x reference)
#include <cuda_runtime.h>

// out[i,c] = 8! * sum_j ( relu(x @ W1 + b1) @ W2 + b2 )[j,c]
// Permutation-symmetry collapse: every row j lands in every position i
// exactly (N-1)! = 40320 times, so the output is row-constant.
//
// Single CTA, 288 threads: warp r computes row r of the hidden layer
// (32 lanes = 32 hidden units; W1 column reads are coalesced 128B/warp,
// x row is a broadcast). Then a 32-thread column reduction and a
// 36-thread epilogue through W2.

static constexpr int N = 9;
static constexpr int D = 512;
static constexpr int H = 32;
static constexpr float FACT8 = 40320.0f;  // (N-1)!

__global__ void __launch_bounds__(N * H, 1)
symmetrization_kernel(const float* __restrict__ x,
                      const float* __restrict__ W1,
                      const float* __restrict__ b1,
                      const float* __restrict__ W2,
                      const float* __restrict__ b2,
                      float* __restrict__ out) {
    __shared__ float h[N * H];   // relu(x @ W1 + b1), row-major [N][H]
    __shared__ float s[H];       // column sums over N rows

    const int t = threadIdx.x;           // 0..287
    const int r = t >> 5;                // row 0..8
    const int k = t & 31;                // hidden unit 0..31

    // ---- hidden layer: h[r][k] = relu( dot(x[r,:], W1[:,k]) + b1[k] ) ----
    const float* xr = x + r * D;
    // 4 independent accumulators to break the FFMA RAW chain (lat=4)
    float a0 = 0.f, a1 = 0.f, a2 = 0.f, a3 = 0.f;
#pragma unroll 8
    for (int d = 0; d < D; d += 4) {
        // W1 is [D][H] row-major: lanes k=0..31 hit consecutive floats -> coalesced
        a0 = fmaf(xr[d + 0], W1[(d + 0) * H + k], a0);
        a1 = fmaf(xr[d + 1], W1[(d + 1) * H + k], a1);
        a2 = fmaf(xr[d + 2], W1[(d + 2) * H + k], a2);
        a3 = fmaf(xr[d + 3], W1[(d + 3) * H + k], a3);
    }
    float acc = (a0 + a1) + (a2 + a3) + b1[k];
    h[t] = fmaxf(acc, 0.0f);
    __syncthreads();

    // ---- column sum over the 9 rows: s[k] = sum_r h[r][k] ----
    if (t < H) {
        float sum = 0.f;
#pragma unroll
        for (int rr = 0; rr < N; rr++) sum += h[rr * H + t];
        s[t] = sum;
    }
    __syncthreads();

    // ---- epilogue: out[r][c] = 40320 * ( sum_j s[j]*W2[j][c] + N*b2[c] ) ----
    if (t < N * 4) {
        const int c = t & 3;  // output feature 0..3
        float v = (float)N * b2[c];
#pragma unroll
        for (int j = 0; j < H; j++) v = fmaf(s[j], W2[j * 4 + c], v);
        out[t] = FACT8 * v;
    }
}

extern "C" void kernel_launch(void* const* d_in, const int* in_sizes, int n_in,
                              void* d_out, int out_size) {
    // metadata order: x[9,512], W1[512,32], b1[32], W2[32,4], b2[4], perms[362880,9]
    const float* x  = (const float*)d_in[0];
    const float* W1 = (const float*)d_in[1];
    const float* b1 = (const float*)d_in[2];
    const float* W2 = (const float*)d_in[3];
    const float* b2 = (const float*)d_in[4];
    // perms (d_in[5]) is provably unused: the permutation sum collapses analytically.
    float* out = (float*)d_out;

    symmetrization_kernel<<<1, N * H>>>(x, W1, b1, W2, b2, out);
}

// round 2
// speedup vs baseline: 1.1910x; 1.1910x over previous
#include <cuda_runtime.h>

// out[i,c] = 8! * sum_j ( relu(x @ W1 + b1) @ W2 + b2 )[j,c]   (row-constant)
//
// R2: one CTA, 512 threads (16 warps, 4/SMSP balanced).
//  - x transposed into smem once (vectorized), so per-d row values are
//    LDS.128 broadcasts.
//  - D split across warps: W1 read exactly once, rank-1-update form.
//  - packed fp32 (fma.rn.f32x2): 4 row-pairs per FFMA2 + 1 scalar row.
//  - fixed-order 16-way reduction of partials => deterministic.

static constexpr int N = 9;
static constexpr int D = 512;
static constexpr int H = 32;
static constexpr int THREADS = 512;
static constexpr int WARPS = 16;
static constexpr int DPW = D / WARPS;   // 32 d-values per warp
static constexpr int XPAD = 12;         // floats per xT row (48B, 16B-aligned)
static constexpr float FACT8 = 40320.0f;  // (N-1)!

__global__ void __launch_bounds__(THREADS, 1)
sym_kernel(const float* __restrict__ x,
           const float* __restrict__ W1,
           const float* __restrict__ b1,
           const float* __restrict__ W2,
           const float* __restrict__ b2,
           float* __restrict__ out) {
    __shared__ float xT[D * XPAD];            // 24576 B : xT[d][r]
    __shared__ float psum[N * H * WARPS];     // 18432 B : [r][k][w]
    __shared__ float h[N * H];
    __shared__ float s[H];

    const int t = threadIdx.x;
    const int w = t >> 5;   // warp 0..15
    const int k = t & 31;   // hidden unit 0..31

    // ---- phase 0: transpose x -> xT[d][r] (float4 global reads) ----
    for (int j = t; j < N * (D / 4); j += THREADS) {
        int r  = j >> 7;             // j / 128
        int d0 = (j & 127) << 2;     // 4-float chunk
        float4 v = *(const float4*)(x + r * D + d0);
        xT[(d0 + 0) * XPAD + r] = v.x;
        xT[(d0 + 1) * XPAD + r] = v.y;
        xT[(d0 + 2) * XPAD + r] = v.z;
        xT[(d0 + 3) * XPAD + r] = v.w;
    }
    __syncthreads();

    // ---- phase 1: partial dot products over this warp's d-chunk ----
    // acc pairs: rows (0,1),(2,3),(4,5),(6,7) packed f32x2; row 8 scalar.
    unsigned long long a01 = 0, a23 = 0, a45 = 0, a67 = 0;
    float a8 = 0.f;
    const float* W1p  = W1 + (w * DPW) * H + k;   // lane k -> coalesced
    const float* xrow = xT + (w * DPW) * XPAD;
#pragma unroll
    for (int i = 0; i < DPW; i++) {
        float wv = W1p[i * H];
        unsigned int wu = __float_as_uint(wv);
        unsigned long long ww;
        asm("mov.b64 %0, {%1, %1};" : "=l"(ww) : "r"(wu));  // (wv, wv)
        const float* xp = xrow + i * XPAD;
        ulonglong2 p0 = *(const ulonglong2*)(xp);      // rows 0..3 (2x f32x2)
        ulonglong2 p1 = *(const ulonglong2*)(xp + 4);  // rows 4..7
        float x8 = xp[8];
        asm("fma.rn.f32x2 %0, %1, %2, %0;" : "+l"(a01) : "l"(p0.x), "l"(ww));
        asm("fma.rn.f32x2 %0, %1, %2, %0;" : "+l"(a23) : "l"(p0.y), "l"(ww));
        asm("fma.rn.f32x2 %0, %1, %2, %0;" : "+l"(a45) : "l"(p1.x), "l"(ww));
        asm("fma.rn.f32x2 %0, %1, %2, %0;" : "+l"(a67) : "l"(p1.y), "l"(ww));
        a8 = fmaf(x8, wv, a8);
    }

    // unpack accumulators and store partials: psum[(r*H + k)*WARPS + w]
    {
        float ar[9];
        unsigned int u0, u1;
        asm("mov.b64 {%0, %1}, %2;" : "=r"(u0), "=r"(u1) : "l"(a01));
        ar[0] = __uint_as_float(u0); ar[1] = __uint_as_float(u1);
        asm("mov.b64 {%0, %1}, %2;" : "=r"(u0), "=r"(u1) : "l"(a23));
        ar[2] = __uint_as_float(u0); ar[3] = __uint_as_float(u1);
        asm("mov.b64 {%0, %1}, %2;" : "=r"(u0), "=r"(u1) : "l"(a45));
        ar[4] = __uint_as_float(u0); ar[5] = __uint_as_float(u1);
        asm("mov.b64 {%0, %1}, %2;" : "=r"(u0), "=r"(u1) : "l"(a67));
        ar[6] = __uint_as_float(u0); ar[7] = __uint_as_float(u1);
        ar[8] = a8;
#pragma unroll
        for (int r = 0; r < N; r++)
            psum[(r * H + k) * WARPS + w] = ar[r];
    }
    __syncthreads();

    // ---- phase 2: reduce 16 partials (fixed order), bias, relu ----
    if (t < N * H) {
        const float* p = psum + t * WARPS;   // 64B-aligned
        float4 q0 = *(const float4*)(p);
        float4 q1 = *(const float4*)(p + 4);
        float4 q2 = *(const float4*)(p + 8);
        float4 q3 = *(const float4*)(p + 12);
        float sum = ((q0.x + q0.y) + (q0.z + q0.w))
                  + ((q1.x + q1.y) + (q1.z + q1.w))
                  + ((q2.x + q2.y) + (q2.z + q2.w))
                  + ((q3.x + q3.y) + (q3.z + q3.w));
        h[t] = fmaxf(sum + b1[k], 0.0f);
    }
    __syncthreads();

    // ---- phase 3: column sums s[k] = sum_r h[r][k] ----
    if (t < H) {
        float sum = 0.f;
#pragma unroll
        for (int rr = 0; rr < N; rr++) sum += h[rr * H + t];
        s[t] = sum;
    }
    __syncthreads();

    // ---- phase 4: out[r][c] = 40320 * (sum_j s[j]*W2[j][c] + N*b2[c]) ----
    if (t < N * 4) {
        const int c = t & 3;
        float v = (float)N * b2[c];
#pragma unroll
        for (int j = 0; j < H; j++) v = fmaf(s[j], W2[j * 4 + c], v);
        out[t] = FACT8 * v;
    }
}

extern "C" void kernel_launch(void* const* d_in, const int* in_sizes, int n_in,
                              void* d_out, int out_size) {
    // metadata order: x[9,512], W1[512,32], b1[32], W2[32,4], b2[4], perms (unused)
    const float* x  = (const float*)d_in[0];
    const float* W1 = (const float*)d_in[1];
    const float* b1 = (const float*)d_in[2];
    const float* W2 = (const float*)d_in[3];
    const float* b2 = (const float*)d_in[4];
    float* out = (float*)d_out;

    sym_kernel<<<1, THREADS>>>(x, W1, b1, W2, b2, out);
}

// round 4
// speedup vs baseline: 1.2239x; 1.0276x over previous
#include <cuda_runtime.h>

// out[i,c] = 8! * sum_j ( relu(x @ W1 + b1) @ W2 + b2 )[j,c]   (row-constant)
//
// R3: single CTA, 512 threads. Key change vs R2: ALL global loads (x, W1,
// b1, W2, b2) are issued before the first __syncthreads, so exactly one
// DRAM latency is exposed instead of four phase-serialized ones. Tail
// reduction runs in warp 0 via shuffle butterflies (fixed tree => bitwise
// deterministic), eliminating a barrier and all tail-phase global traffic.

static constexpr int N = 9;
static constexpr int D = 512;
static constexpr int H = 32;
static constexpr int THREADS = 512;
static constexpr int WARPS = 16;
static constexpr int DPW = D / WARPS;     // 32 d-values per warp
static constexpr int XPAD = 12;           // floats per xT row (48B, 16B aligned)
static constexpr float FACT8 = 40320.0f;  // (N-1)!

__global__ void __launch_bounds__(THREADS, 1)
sym_kernel(const float* __restrict__ x,
           const float* __restrict__ W1,
           const float* __restrict__ b1,
           const float* __restrict__ W2,
           const float* __restrict__ b2,
           float* __restrict__ out) {
    __shared__ float xT[D * XPAD];          // xT[d][r]
    __shared__ float psum[N * H * WARPS];   // [r][k][w]
    __shared__ float h[N * H];

    const int t = threadIdx.x;
    const int w = t >> 5;   // warp 0..15
    const int k = t & 31;   // lane / hidden unit

    // ---- prefetch EVERYTHING before the first barrier ----
    // W1 chunk for this warp -> registers (lane k coalesced, 128B/req)
    float wreg[DPW];
    const float* W1p = W1 + (w * DPW) * H + k;
#pragma unroll
    for (int i = 0; i < DPW; i++) wreg[i] = W1p[i * H];

    // bias for the h-phase (every thread; tiny, L2-broadcast after 1st warp)
    const float b1r = b1[k];

    // tail operands live only in warp 0
    float4 w2r = make_float4(0.f, 0.f, 0.f, 0.f);
    float  b2r = 0.f;
    if (w == 0) {
        w2r = *(const float4*)(W2 + k * 4);   // W2 row j=k
        if (k < 4) b2r = b2[k];
    }

    // x transpose into smem (float4 global reads), issued alongside W1 LDGs
    for (int j = t; j < N * (D / 4); j += THREADS) {
        int r  = j >> 7;            // row 0..8
        int d0 = (j & 127) << 2;    // 4-float chunk
        float4 v = *(const float4*)(x + r * D + d0);
        xT[(d0 + 0) * XPAD + r] = v.x;
        xT[(d0 + 1) * XPAD + r] = v.y;
        xT[(d0 + 2) * XPAD + r] = v.z;
        xT[(d0 + 3) * XPAD + r] = v.w;
    }
    __syncthreads();

    // ---- rank-1-update partial dots over this warp's d-chunk ----
    // rows (0,1),(2,3),(4,5),(6,7) as packed f32x2; row 8 scalar.
    unsigned long long a01 = 0, a23 = 0, a45 = 0, a67 = 0;
    float a8 = 0.f;
    const float* xrow = xT + (w * DPW) * XPAD;
#pragma unroll
    for (int i = 0; i < DPW; i++) {
        float wv = wreg[i];
        unsigned int wu = __float_as_uint(wv);
        unsigned long long ww;
        asm("mov.b64 %0, {%1, %1};" : "=l"(ww) : "r"(wu));
        const float* xp = xrow + i * XPAD;
        ulonglong2 p0 = *(const ulonglong2*)(xp);       // rows 0..3
        ulonglong2 p1 = *(const ulonglong2*)(xp + 4);   // rows 4..7
        float x8 = xp[8];
        asm("fma.rn.f32x2 %0, %1, %2, %0;" : "+l"(a01) : "l"(p0.x), "l"(ww));
        asm("fma.rn.f32x2 %0, %1, %2, %0;" : "+l"(a23) : "l"(p0.y), "l"(ww));
        asm("fma.rn.f32x2 %0, %1, %2, %0;" : "+l"(a45) : "l"(p1.x), "l"(ww));
        asm("fma.rn.f32x2 %0, %1, %2, %0;" : "+l"(a67) : "l"(p1.y), "l"(ww));
        a8 = fmaf(x8, wv, a8);
    }
    {
        float ar[9];
        unsigned int u0, u1;
        asm("mov.b64 {%0, %1}, %2;" : "=r"(u0), "=r"(u1) : "l"(a01));
        ar[0] = __uint_as_float(u0); ar[1] = __uint_as_float(u1);
        asm("mov.b64 {%0, %1}, %2;" : "=r"(u0), "=r"(u1) : "l"(a23));
        ar[2] = __uint_as_float(u0); ar[3] = __uint_as_float(u1);
        asm("mov.b64 {%0, %1}, %2;" : "=r"(u0), "=r"(u1) : "l"(a45));
        ar[4] = __uint_as_float(u0); ar[5] = __uint_as_float(u1);
        asm("mov.b64 {%0, %1}, %2;" : "=r"(u0), "=r"(u1) : "l"(a67));
        ar[6] = __uint_as_float(u0); ar[7] = __uint_as_float(u1);
        ar[8] = a8;
#pragma unroll
        for (int r = 0; r < N; r++)
            psum[(r * H + k) * WARPS + w] = ar[r];
    }
    __syncthreads();

    // ---- reduce the 16 warp partials (fixed order), bias, relu ----
    if (t < N * H) {
        const float* p = psum + t * WARPS;    // 64B aligned
        float4 q0 = *(const float4*)(p);
        float4 q1 = *(const float4*)(p + 4);
        float4 q2 = *(const float4*)(p + 8);
        float4 q3 = *(const float4*)(p + 12);
        float sum = ((q0.x + q0.y) + (q0.z + q0.w))
                  + ((q1.x + q1.y) + (q1.z + q1.w))
                  + ((q2.x + q2.y) + (q2.z + q2.w))
                  + ((q3.x + q3.y) + (q3.z + q3.w));
        h[t] = fmaxf(sum + b1r, 0.0f);
    }
    __syncthreads();

    // ---- warp 0 finishes everything with shuffles (no more barriers) ----
    if (w == 0) {
        // s_k = sum_r h[r][k]   (conflict-free: stride 32)
        float s = 0.f;
#pragma unroll
        for (int r = 0; r < N; r++) s += h[r * H + k];

        // v_c = sum_j s_j * W2[j][c] via xor-butterfly (fixed tree, det.)
        float v0 = s * w2r.x, v1 = s * w2r.y, v2 = s * w2r.z, v3 = s * w2r.w;
#pragma unroll
        for (int off = 16; off; off >>= 1) {
            v0 += __shfl_xor_sync(0xffffffffu, v0, off);
            v1 += __shfl_xor_sync(0xffffffffu, v1, off);
            v2 += __shfl_xor_sync(0xffffffffu, v2, off);
            v3 += __shfl_xor_sync(0xffffffffu, v3, off);
        }

        const int c = k & 3;
        float b2c  = __shfl_sync(0xffffffffu, b2r, c);  // b2[c] from lanes 0..3
        float vsel = (c == 0) ? v0 : (c == 1) ? v1 : (c == 2) ? v2 : v3;
        float val  = FACT8 * fmaf((float)N, b2c, vsel);

        out[k] = val;                       // positions 0..31
        if (k < 4) out[32 + k] = val;       // positions 32..35 (row 8)
    }
}

extern "C" void kernel_launch(void* const* d_in, const int* in_sizes, int n_in,
                              void* d_out, int out_size) {
    // metadata order: x[9,512], W1[512,32], b1[32], W2[32,4], b2[4], perms (unused)
    const float* x  = (const float*)d_in[0];
    const float* W1 = (const float*)d_in[1];
    const float* b1 = (const float*)d_in[2];
    const float* W2 = (const float*)d_in[3];
    const float* b2 = (const float*)d_in[4];
    float* out = (float*)d_out;

    sym_kernel<<<1, THREADS>>>(x, W1, b1, W2, b2, out);
}

// round 5
// speedup vs baseline: 1.9275x; 1.5749x over previous
#include <cuda_runtime.h>

// out[i,c] = 8! * sum_j ( relu(x @ W1 + b1) @ W2 + b2 )[j,c]   (row-constant)
//
// R5: same algorithm as R3, but smem layouts rebuilt to kill bank conflicts:
//  - x transpose done scalar-wise (lane stride = XPAD=12 -> 4-way max,
//    was 16-way), LDGs still coalesced.
//  - psum relaid out as [w][r*H+k]: stores and reduction reads conflict-free
//    (was 16-way on stores, 4-way on loads).
// Mainloop LDS are same-address broadcasts (conflict-free) and unchanged.

static constexpr int N = 9;
static constexpr int D = 512;
static constexpr int H = 32;
static constexpr int THREADS = 512;
static constexpr int WARPS = 16;
static constexpr int DPW = D / WARPS;     // 32 d-values per warp
static constexpr int XPAD = 12;           // floats per xT row (48B, 16B aligned)
static constexpr float FACT8 = 40320.0f;  // (N-1)!

__global__ void __launch_bounds__(THREADS, 1)
sym_kernel(const float* __restrict__ x,
           const float* __restrict__ W1,
           const float* __restrict__ b1,
           const float* __restrict__ W2,
           const float* __restrict__ b2,
           float* __restrict__ out) {
    __shared__ float xT[D * XPAD];          // xT[d][r], row-aligned to 48B
    __shared__ float psum[WARPS * N * H];   // [w][r*H + k]  (conflict-free)
    __shared__ float h[N * H];

    const int t = threadIdx.x;
    const int w = t >> 5;   // warp 0..15
    const int k = t & 31;   // lane / hidden unit

    // ---- prefetch everything before the first barrier ----
    // x transpose: thread t owns column d=t; 9 coalesced scalar LDGs,
    // STS lane stride = XPAD (4-way worst case).
#pragma unroll
    for (int r = 0; r < N; r++)
        xT[t * XPAD + r] = x[r * D + t];

    // W1 chunk for this warp -> registers (lane k coalesced, 128B/req)
    float wreg[DPW];
    const float* W1p = W1 + (w * DPW) * H + k;
#pragma unroll
    for (int i = 0; i < DPW; i++) wreg[i] = W1p[i * H];

    const float b1r = b1[k];

    // tail operands live only in warp 0
    float4 w2r = make_float4(0.f, 0.f, 0.f, 0.f);
    float  b2r = 0.f;
    if (w == 0) {
        w2r = *(const float4*)(W2 + k * 4);
        if (k < 4) b2r = b2[k];
    }
    __syncthreads();

    // ---- rank-1-update partial dots over this warp's d-chunk ----
    // rows (0,1),(2,3),(4,5),(6,7) packed f32x2; row 8 scalar.
    unsigned long long a01 = 0, a23 = 0, a45 = 0, a67 = 0;
    float a8 = 0.f;
    const float* xrow = xT + (w * DPW) * XPAD;
#pragma unroll
    for (int i = 0; i < DPW; i++) {
        float wv = wreg[i];
        unsigned int wu = __float_as_uint(wv);
        unsigned long long ww;
        asm("mov.b64 %0, {%1, %1};" : "=l"(ww) : "r"(wu));
        const float* xp = xrow + i * XPAD;               // 48B-aligned
        ulonglong2 p0 = *(const ulonglong2*)(xp);        // rows 0..3 (broadcast)
        ulonglong2 p1 = *(const ulonglong2*)(xp + 4);    // rows 4..7
        float x8 = xp[8];
        asm("fma.rn.f32x2 %0, %1, %2, %0;" : "+l"(a01) : "l"(p0.x), "l"(ww));
        asm("fma.rn.f32x2 %0, %1, %2, %0;" : "+l"(a23) : "l"(p0.y), "l"(ww));
        asm("fma.rn.f32x2 %0, %1, %2, %0;" : "+l"(a45) : "l"(p1.x), "l"(ww));
        asm("fma.rn.f32x2 %0, %1, %2, %0;" : "+l"(a67) : "l"(p1.y), "l"(ww));
        a8 = fmaf(x8, wv, a8);
    }
    {
        float ar[9];
        unsigned int u0, u1;
        asm("mov.b64 {%0, %1}, %2;" : "=r"(u0), "=r"(u1) : "l"(a01));
        ar[0] = __uint_as_float(u0); ar[1] = __uint_as_float(u1);
        asm("mov.b64 {%0, %1}, %2;" : "=r"(u0), "=r"(u1) : "l"(a23));
        ar[2] = __uint_as_float(u0); ar[3] = __uint_as_float(u1);
        asm("mov.b64 {%0, %1}, %2;" : "=r"(u0), "=r"(u1) : "l"(a45));
        ar[4] = __uint_as_float(u0); ar[5] = __uint_as_float(u1);
        asm("mov.b64 {%0, %1}, %2;" : "=r"(u0), "=r"(u1) : "l"(a67));
        ar[6] = __uint_as_float(u0); ar[7] = __uint_as_float(u1);
        ar[8] = a8;
        // conflict-free: lane stride 1 within each STS
        float* pp = psum + w * (N * H) + k;
#pragma unroll
        for (int r = 0; r < N; r++) pp[r * H] = ar[r];
    }
    __syncthreads();

    // ---- reduce the 16 warp partials (fixed order), bias, relu ----
    if (t < N * H) {
        float q[WARPS];
#pragma unroll
        for (int ww2 = 0; ww2 < WARPS; ww2++)
            q[ww2] = psum[ww2 * (N * H) + t];   // consecutive-per-thread: CF
        float sum = (((q[0] + q[1]) + (q[2] + q[3])) + ((q[4] + q[5]) + (q[6] + q[7])))
                  + (((q[8] + q[9]) + (q[10] + q[11])) + ((q[12] + q[13]) + (q[14] + q[15])));
        h[t] = fmaxf(sum + b1r, 0.0f);
    }
    __syncthreads();

    // ---- warp 0 finishes with shuffles (fixed tree, deterministic) ----
    if (w == 0) {
        float s = 0.f;
#pragma unroll
        for (int r = 0; r < N; r++) s += h[r * H + k];

        float v0 = s * w2r.x, v1 = s * w2r.y, v2 = s * w2r.z, v3 = s * w2r.w;
#pragma unroll
        for (int off = 16; off; off >>= 1) {
            v0 += __shfl_xor_sync(0xffffffffu, v0, off);
            v1 += __shfl_xor_sync(0xffffffffu, v1, off);
            v2 += __shfl_xor_sync(0xffffffffu, v2, off);
            v3 += __shfl_xor_sync(0xffffffffu, v3, off);
        }

        const int c = k & 3;
        float b2c  = __shfl_sync(0xffffffffu, b2r, c);
        float vsel = (c == 0) ? v0 : (c == 1) ? v1 : (c == 2) ? v2 : v3;
        float val  = FACT8 * fmaf((float)N, b2c, vsel);

        out[k] = val;                   // positions 0..31
        if (k < 4) out[32 + k] = val;   // positions 32..35
    }
}

extern "C" void kernel_launch(void* const* d_in, const int* in_sizes, int n_in,
                              void* d_out, int out_size) {
    // metadata order: x[9,512], W1[512,32], b1[32], W2[32,4], b2[4], perms (unused)
    const float* x  = (const float*)d_in[0];
    const float* W1 = (const float*)d_in[1];
    const float* b1 = (const float*)d_in[2];
    const float* W2 = (const float*)d_in[3];
    const float* b2 = (const float*)d_in[4];
    float* out = (float*)d_out;

    sym_kernel<<<1, THREADS>>>(x, W1, b1, W2, b2, out);
}